// round 16
// baseline (speedup 1.0000x reference)
#include <cuda_runtime.h>
#include <cuda_fp16.h>
#include <cstdint>

// GraphAttentionLayer: B=8, N=2048, Fin=Fout=256
//  K1: Wh = h @ W^T  (tf32 mma.sync, 128x256 blocks, single wave)  [30.2us]
//  K2: per-row E1=exp(f1), F1=exp(.2 f1), EF=(exp(f2), exp(.2 f2))
//  K2.5 (wgen): w[i][j] fp16 + fp32 row denominators (streaming, ~34us)
//  K3: pure fp16 m16n8k16 GEMM out = (w @ Whh)/den, depth-6 ring,
//      chunk-PAIR processing: one wait+barrier per 2 chunks.

#define NROW   2048
#define FDIM   256
#define NBATCH 8
#define NTOT   (NBATCH * NROW)

#define K1ST 36
#define KJ   32
#define NIT  (NROW / KJ)   // 64

// ---------------- scratch ----------------
__device__ float  g_Wh [NTOT * FDIM];
__device__ __half g_Whh[NTOT * FDIM];
__device__ float  g_E1[NTOT], g_F1[NTOT];
__device__ float2 g_EF[NTOT];
__device__ __half g_W  [(size_t)NTOT * NROW];   // 67 MB fp16 attention weights
__device__ float  g_den[NTOT];

// ---------------- helpers ----------------
__device__ __forceinline__ uint32_t to_tf32(float x) {
    uint32_t r; asm("cvt.rna.tf32.f32 %0, %1;" : "=r"(r) : "f"(x)); return r;
}
__device__ __forceinline__ void mma_tf32(float* d, const uint32_t* a, const uint32_t* b) {
    asm volatile(
        "mma.sync.aligned.m16n8k8.row.col.f32.tf32.tf32.f32 "
        "{%0,%1,%2,%3}, {%4,%5,%6,%7}, {%8,%9}, {%0,%1,%2,%3};"
        : "+f"(d[0]), "+f"(d[1]), "+f"(d[2]), "+f"(d[3])
        : "r"(a[0]), "r"(a[1]), "r"(a[2]), "r"(a[3]), "r"(b[0]), "r"(b[1]));
}
__device__ __forceinline__ void mma_f16(float* d, const uint32_t* a, const uint32_t* b) {
    asm volatile(
        "mma.sync.aligned.m16n8k16.row.col.f32.f16.f16.f32 "
        "{%0,%1,%2,%3}, {%4,%5,%6,%7}, {%8,%9}, {%0,%1,%2,%3};"
        : "+f"(d[0]), "+f"(d[1]), "+f"(d[2]), "+f"(d[3])
        : "r"(a[0]), "r"(a[1]), "r"(a[2]), "r"(a[3]), "r"(b[0]), "r"(b[1]));
}
__device__ __forceinline__ void ldm_x4(uint32_t* r, const void* p) {
    uint32_t a = (uint32_t)__cvta_generic_to_shared(p);
    asm volatile("ldmatrix.sync.aligned.m8n8.x4.shared.b16 {%0,%1,%2,%3}, [%4];"
                 : "=r"(r[0]), "=r"(r[1]), "=r"(r[2]), "=r"(r[3]) : "r"(a));
}
__device__ __forceinline__ void ldm_x4_t(uint32_t* r, const void* p) {
    uint32_t a = (uint32_t)__cvta_generic_to_shared(p);
    asm volatile("ldmatrix.sync.aligned.m8n8.x4.trans.shared.b16 {%0,%1,%2,%3}, [%4];"
                 : "=r"(r[0]), "=r"(r[1]), "=r"(r[2]), "=r"(r[3]) : "r"(a));
}
__device__ __forceinline__ void cp_async16(void* dst, const void* src) {
    uint32_t d = (uint32_t)__cvta_generic_to_shared(dst);
    asm volatile("cp.async.cg.shared.global [%0], [%1], 16;" :: "r"(d), "l"(src));
}
#define CP_COMMIT() asm volatile("cp.async.commit_group;" ::: "memory")
#define CP_WAIT2()  asm volatile("cp.async.wait_group 2;" ::: "memory")

// =====================================================================
// Kernel 1: Wh = h @ W^T, tf32 mma, 128n x 256o blocks, 512 threads.
// =====================================================================
__global__ void __launch_bounds__(512, 1) wh_mma_kernel(
    const float* __restrict__ h, const float* __restrict__ W,
    float* __restrict__ Wh, __half* __restrict__ Whh)
{
    extern __shared__ uint32_t sm1[];
    uint32_t* sA = sm1;                      // [2][128][K1ST]
    uint32_t* sB = sm1 + 2 * 128 * K1ST;     // [2][256][K1ST]

    const int t = threadIdx.x, wid = t >> 5, lid = t & 31;
    const int n0 = blockIdx.x * 128;
    const int rh = t >> 2, sh = (t & 3) * 8;
    const int rw = t >> 1, sw = (t & 1) * 16;
    const int wi = wid & 3, wo = wid >> 2;
    const int g = lid >> 2, tig = lid & 3;

    const float* hp = h + (size_t)(n0 + rh) * FDIM + sh;
    const float* wp = W + (size_t)rw * FDIM + sw;

    float d[2][8][4];
#pragma unroll
    for (int mi = 0; mi < 2; mi++)
#pragma unroll
        for (int ni = 0; ni < 8; ni++)
#pragma unroll
            for (int q = 0; q < 4; q++) d[mi][ni][q] = 0.f;

    float4 hr[2], wr[4];

    auto ldg = [&](int it) {
        const int f0 = it * 32;
        hr[0] = *(const float4*)(hp + f0);
        hr[1] = *(const float4*)(hp + f0 + 4);
#pragma unroll
        for (int q = 0; q < 4; q++)
            wr[q] = *(const float4*)(wp + f0 + q * 4);
    };
    auto sts = [&](int bf) {
        uint32_t* ab = sA + bf * 128 * K1ST + rh * K1ST + sh;
        uint32_t* bb = sB + bf * 256 * K1ST + rw * K1ST + sw;
#pragma unroll
        for (int q = 0; q < 2; q++)
            *(uint4*)(ab + q * 4) = make_uint4(to_tf32(hr[q].x), to_tf32(hr[q].y),
                                               to_tf32(hr[q].z), to_tf32(hr[q].w));
#pragma unroll
        for (int q = 0; q < 4; q++)
            *(uint4*)(bb + q * 4) = make_uint4(to_tf32(wr[q].x), to_tf32(wr[q].y),
                                               to_tf32(wr[q].z), to_tf32(wr[q].w));
    };
    auto mma_phase = [&](int bf) {
        const uint32_t* A = sA + bf * 128 * K1ST;
        const uint32_t* B = sB + bf * 256 * K1ST;
#pragma unroll
        for (int ks = 0; ks < 4; ks++) {
            uint32_t af[2][4];
#pragma unroll
            for (int mi = 0; mi < 2; mi++) {
                const int row = wi * 32 + mi * 16 + g;
                const int kc  = ks * 8 + tig;
                af[mi][0] = A[row * K1ST + kc];
                af[mi][1] = A[(row + 8) * K1ST + kc];
                af[mi][2] = A[row * K1ST + kc + 4];
                af[mi][3] = A[(row + 8) * K1ST + kc + 4];
            }
            uint32_t bfr[8][2];
#pragma unroll
            for (int ni = 0; ni < 8; ni++) {
                const int col = wo * 64 + ni * 8 + g;
                const int kc  = ks * 8 + tig;
                bfr[ni][0] = B[col * K1ST + kc];
                bfr[ni][1] = B[col * K1ST + kc + 4];
            }
#pragma unroll
            for (int mi = 0; mi < 2; mi++)
#pragma unroll
                for (int ni = 0; ni < 8; ni++)
                    mma_tf32(d[mi][ni], af[mi], bfr[ni]);
        }
    };

    ldg(0); sts(0); __syncthreads();
    for (int it = 0; it < 8; it++) {
        if (it + 1 < 8) ldg(it + 1);
        mma_phase(it & 1);
        if (it + 1 < 8) sts((it + 1) & 1);
        __syncthreads();
    }

#pragma unroll
    for (int mi = 0; mi < 2; mi++) {
        const int r0 = wi * 32 + mi * 16 + g;
        const int r1 = r0 + 8;
        float*  o0p = Wh + (size_t)(n0 + r0) * FDIM + wo * 64 + tig * 2;
        float*  o1p = Wh + (size_t)(n0 + r1) * FDIM + wo * 64 + tig * 2;
        __half* h0p = Whh + (size_t)(n0 + r0) * FDIM + wo * 64 + tig * 2;
        __half* h1p = Whh + (size_t)(n0 + r1) * FDIM + wo * 64 + tig * 2;
#pragma unroll
        for (int ni = 0; ni < 8; ni++) {
            *(float2*)(o0p + ni * 8) = make_float2(d[mi][ni][0], d[mi][ni][1]);
            *(float2*)(o1p + ni * 8) = make_float2(d[mi][ni][2], d[mi][ni][3]);
            *(__half2*)(h0p + ni * 8) =
                __float22half2_rn(make_float2(d[mi][ni][0], d[mi][ni][1]));
            *(__half2*)(h1p + ni * 8) =
                __float22half2_rn(make_float2(d[mi][ni][2], d[mi][ni][3]));
        }
    }
}

// =====================================================================
// Kernel 2: per-row f1,f2 -> E1, F1, (E2,F2)
// =====================================================================
__global__ void __launch_bounds__(256) fvec_kernel(
    const float* __restrict__ Wh, const float* __restrict__ a,
    float* __restrict__ E1, float* __restrict__ F1, float2* __restrict__ EF)
{
    const int row  = blockIdx.x * 8 + (threadIdx.x >> 5);
    const int lane = threadIdx.x & 31;
    const float4* wr = (const float4*)(Wh + (size_t)row * FDIM);
    const float4* a1 = (const float4*)a;
    const float4* a2 = (const float4*)(a + FDIM);

    float4 x0 = wr[lane], x1 = wr[lane + 32];
    float4 p0 = a1[lane], p1 = a1[lane + 32];
    float4 q0 = a2[lane], q1 = a2[lane + 32];

    float s1 = x0.x * p0.x + x0.y * p0.y + x0.z * p0.z + x0.w * p0.w
             + x1.x * p1.x + x1.y * p1.y + x1.z * p1.z + x1.w * p1.w;
    float s2 = x0.x * q0.x + x0.y * q0.y + x0.z * q0.z + x0.w * q0.w
             + x1.x * q1.x + x1.y * q1.y + x1.z * q1.z + x1.w * q1.w;
#pragma unroll
    for (int o = 16; o; o >>= 1) {
        s1 += __shfl_xor_sync(0xFFFFFFFFu, s1, o);
        s2 += __shfl_xor_sync(0xFFFFFFFFu, s2, o);
    }
    if (lane == 0) {
        E1[row] = __expf(s1);
        F1[row] = __expf(0.2f * s1);
        EF[row] = make_float2(__expf(s2), __expf(0.2f * s2));
    }
}

// =====================================================================
// Kernel 2.5 (wgen): fp16 w matrix + fp32 row denominators (streaming).
// =====================================================================
__global__ void __launch_bounds__(512) wgen_kernel(
    const int* __restrict__ adj,
    const float* __restrict__ E1, const float* __restrict__ F1,
    const float2* __restrict__ EF,
    __half* __restrict__ wmat, float* __restrict__ den)
{
    __shared__ float2 sEF[NROW];   // 16 KB
    const int t = threadIdx.x, wrp = t >> 5, lane = t & 31;
    const int bz = blockIdx.y;

    {
        const float4* src = (const float4*)(EF + bz * NROW);
        float4* dst = (float4*)sEF;
        dst[t]       = src[t];
        dst[t + 512] = src[t + 512];
    }
    __syncthreads();

    const int row_g = bz * NROW + blockIdx.x * 16 + wrp;
    const float E1r  = E1[row_g], F1r = F1[row_g];
    const float tinv = __frcp_rn(E1r);            // s>0  <=>  E2_j > 1/E1_i

    const int4* ap = (const int4*)(adj + (size_t)row_g * NROW);
    __half* wp = wmat + (size_t)row_g * NROW;

    float dn = 0.f;
#pragma unroll 4
    for (int c = 0; c < 16; c++) {
        const int j0 = c * 128 + lane * 4;
        const int4 am = __ldg(ap + c * 32 + lane);
        const float4 efa = *(const float4*)(sEF + j0);
        const float4 efb = *(const float4*)(sEF + j0 + 2);
        float w0 = am.x ? (efa.x > tinv ? E1r * efa.x : F1r * efa.y) : 0.f;
        float w1 = am.y ? (efa.z > tinv ? E1r * efa.z : F1r * efa.w) : 0.f;
        float w2 = am.z ? (efb.x > tinv ? E1r * efb.x : F1r * efb.y) : 0.f;
        float w3 = am.w ? (efb.z > tinv ? E1r * efb.z : F1r * efb.w) : 0.f;
        dn += (w0 + w1) + (w2 + w3);
        __half2 p0 = __float22half2_rn(make_float2(w0, w1));
        __half2 p1 = __float22half2_rn(make_float2(w2, w3));
        uint2 pk = make_uint2(*(uint32_t*)&p0, *(uint32_t*)&p1);
        *(uint2*)(wp + j0) = pk;
    }
#pragma unroll
    for (int o = 16; o; o >>= 1)
        dn += __shfl_xor_sync(0xFFFFFFFFu, dn, o);
    if (lane == 0) den[row_g] = dn;
}

// =====================================================================
// Kernel 3: pure fp16 GEMM, 128i x 256o, 512 threads, depth-6 ring,
// chunk pairs: one wait_group + one barrier per 2 chunks.
// =====================================================================
#define AST3 40            // A tile row stride (halves): 32 + 8 pad
#define BST3 264           // B tile k-row stride (halves): 256 + 8 pad
#define A_SLOT (128 * AST3 * 2)   // 10240 B
#define B_SLOT (32 * BST3 * 2)    // 16896 B
// smem layout (bytes)
#define OFF_A   0          // A ring: 6 * 10240 = 61440
#define OFF_B   61440      // B ring: 6 * 16896 = 101376
#define SM3_SZ  162816

__global__ void __launch_bounds__(512, 1) attn_f16_kernel(
    const __half* __restrict__ wmat,
    const __half* __restrict__ Whh,
    const float* __restrict__ den,
    float* __restrict__ out)
{
    extern __shared__ char smc[];
    __half* smA = (__half*)(smc + OFF_A);
    __half* smB = (__half*)(smc + OFF_B);

    const int t = threadIdx.x, wid = t >> 5, lid = t & 31;
    const int bz = blockIdx.y, i0 = blockIdx.x * 128;
    const int wi = wid & 3, wo = wid >> 2;       // warp tile: rows wi*32, cols wo*64
    const int g  = lid >> 2, tig = lid & 3;

    const char* w_src   = (const char*)(wmat + (size_t)(bz * NROW + i0 + (t >> 2)) * NROW)
                          + (t & 3) * 16;
    const char* whh_src = (const char*)(Whh + (size_t)(bz * NROW + (t & 31)) * FDIM)
                          + (t >> 5) * 16;

    auto stage = [&](int c) {
        const int slot = c % 6;
        {
            char* dst = (char*)smA + slot * A_SLOT
                        + (t >> 2) * (AST3 * 2) + (t & 3) * 16;
            cp_async16(dst, w_src + (size_t)c * (KJ * 2));
        }
        {
            char* dst = (char*)smB + slot * B_SLOT
                        + (t & 31) * (BST3 * 2) + (t >> 5) * 16;
            const char* src = whh_src + (size_t)c * (KJ * FDIM * 2);
            cp_async16(dst, src);
            cp_async16(dst + 256, src + 256);
        }
    };

    float d[2][8][4];
#pragma unroll
    for (int mi = 0; mi < 2; mi++)
#pragma unroll
        for (int ni = 0; ni < 8; ni++)
#pragma unroll
            for (int q = 0; q < 4; q++) d[mi][ni][q] = 0.f;

    auto mma_phase = [&](int c) {
        const __half* A = smA + (c % 6) * (128 * AST3);
        const __half* B = smB + (c % 6) * (32 * BST3);
#pragma unroll
        for (int ks = 0; ks < 2; ks++) {
            uint32_t af[2][4];
#pragma unroll
            for (int mi = 0; mi < 2; mi++)
                ldm_x4(af[mi], A + (wi * 32 + mi * 16 + (lid & 15)) * AST3
                               + ks * 16 + (lid >> 4) * 8);
            uint32_t bf4[4][4];
#pragma unroll
            for (int np = 0; np < 4; np++)
                ldm_x4_t(bf4[np], B + (ks * 16 + (lid & 7) + ((lid >> 3) & 1) * 8) * BST3
                                  + wo * 64 + np * 16 + (lid >> 4) * 8);
#pragma unroll
            for (int mi = 0; mi < 2; mi++)
#pragma unroll
                for (int ni = 0; ni < 8; ni++)
                    mma_f16(d[mi][ni], af[mi], &bf4[ni >> 1][(ni & 1) * 2]);
        }
    };

    // ---- prologue: 4 groups in flight ----
    stage(0); CP_COMMIT();
    stage(1); CP_COMMIT();
    stage(2); CP_COMMIT();
    stage(3); CP_COMMIT();

    // ---- main loop: pairs of chunks; commits = c+4 at iteration top ----
    for (int c = 0; c < NIT; c += 2) {
        CP_WAIT2();                  // groups <= c+1 complete
        __syncthreads();             // slots c, c+1 visible; mma(c-2),(c-1) retired
        if (c + 4 < NIT) stage(c + 4);
        CP_COMMIT();
        if (c + 5 < NIT) stage(c + 5);
        CP_COMMIT();
        mma_phase(c);
        mma_phase(c + 1);
    }

    // ---- epilogue ----
    const float* denb = den + bz * NROW + i0;
#pragma unroll
    for (int mi = 0; mi < 2; mi++) {
        const int r0 = wi * 32 + mi * 16 + g;
        const int r1 = r0 + 8;
        const float inv0 = 1.0f / denb[r0];
        const float inv1 = 1.0f / denb[r1];
        float* op0 = out + (size_t)(bz * NROW + i0 + r0) * FDIM + wo * 64 + tig * 2;
        float* op1 = out + (size_t)(bz * NROW + i0 + r1) * FDIM + wo * 64 + tig * 2;
#pragma unroll
        for (int ni = 0; ni < 8; ni++) {
            *(float2*)(op0 + ni * 8) = make_float2(d[mi][ni][0] * inv0, d[mi][ni][1] * inv0);
            *(float2*)(op1 + ni * 8) = make_float2(d[mi][ni][2] * inv1, d[mi][ni][3] * inv1);
        }
    }
}

// =====================================================================
extern "C" void kernel_launch(void* const* d_in, const int* in_sizes, int n_in,
                              void* d_out, int out_size)
{
    const float* h   = (const float*)d_in[0];
    const int*   adj = (const int*)  d_in[1];
    const float* W   = (const float*)d_in[2];
    const float* a   = (const float*)d_in[3];
    float* out = (float*)d_out;

    float *Wh, *E1, *F1, *den;
    float2* EFp;
    __half *Whh, *wmat;
    cudaGetSymbolAddress((void**)&Wh,   g_Wh);
    cudaGetSymbolAddress((void**)&Whh,  g_Whh);
    cudaGetSymbolAddress((void**)&E1,   g_E1);
    cudaGetSymbolAddress((void**)&F1,   g_F1);
    cudaGetSymbolAddress((void**)&EFp,  g_EF);
    cudaGetSymbolAddress((void**)&wmat, g_W);
    cudaGetSymbolAddress((void**)&den,  g_den);

    const int smem1 = (2 * 128 * K1ST + 2 * 256 * K1ST) * (int)sizeof(uint32_t); // 110592
    cudaFuncSetAttribute(wh_mma_kernel,   cudaFuncAttributeMaxDynamicSharedMemorySize, smem1);
    cudaFuncSetAttribute(attn_f16_kernel, cudaFuncAttributeMaxDynamicSharedMemorySize, SM3_SZ);

    wh_mma_kernel<<<NTOT / 128, 512, smem1>>>(h, W, Wh, Whh);
    fvec_kernel<<<NTOT / 8, 256>>>(Wh, a, E1, F1, EFp);
    wgen_kernel<<<dim3(NROW / 16, NBATCH), 512>>>(adj, E1, F1, EFp, wmat, den);
    attn_f16_kernel<<<dim3(NROW / 128, NBATCH), 512, SM3_SZ>>>(wmat, Whh, den, out);
}

// round 17
// speedup vs baseline: 1.1712x; 1.1712x over previous
#include <cuda_runtime.h>
#include <cuda_fp16.h>
#include <cstdint>

// GraphAttentionLayer: B=8, N=2048, Fin=Fout=256
//  K1: Wh = h @ W^T  (tf32 mma.sync, 128x256 blocks, single wave)  [30.2us]
//  K2: per-row E1=exp(f1), F1=exp(.2 f1), EF=(exp(f2), exp(.2 f2))
//  K2.5 (wgen): w[i][j] fp16 + fp32 row denominators (streaming, ~34us)
//  K3: pure fp16 m16n8k16 GEMM out = (w @ Whh)/den, 128i x 128o tiles,
//      256 thr, 2 blocks/SM (barrier gaps of one block filled by the other),
//      depth-4 cp.async ring, per-chunk wait (R13's overlap preserved).

#define NROW   2048
#define FDIM   256
#define NBATCH 8
#define NTOT   (NBATCH * NROW)

#define K1ST 36
#define KJ   32
#define NIT  (NROW / KJ)   // 64

// ---------------- scratch ----------------
__device__ float  g_Wh [NTOT * FDIM];
__device__ __half g_Whh[NTOT * FDIM];
__device__ float  g_E1[NTOT], g_F1[NTOT];
__device__ float2 g_EF[NTOT];
__device__ __half g_W  [(size_t)NTOT * NROW];   // 67 MB fp16 attention weights
__device__ float  g_den[NTOT];

// ---------------- helpers ----------------
__device__ __forceinline__ uint32_t to_tf32(float x) {
    uint32_t r; asm("cvt.rna.tf32.f32 %0, %1;" : "=r"(r) : "f"(x)); return r;
}
__device__ __forceinline__ void mma_tf32(float* d, const uint32_t* a, const uint32_t* b) {
    asm volatile(
        "mma.sync.aligned.m16n8k8.row.col.f32.tf32.tf32.f32 "
        "{%0,%1,%2,%3}, {%4,%5,%6,%7}, {%8,%9}, {%0,%1,%2,%3};"
        : "+f"(d[0]), "+f"(d[1]), "+f"(d[2]), "+f"(d[3])
        : "r"(a[0]), "r"(a[1]), "r"(a[2]), "r"(a[3]), "r"(b[0]), "r"(b[1]));
}
__device__ __forceinline__ void mma_f16(float* d, const uint32_t* a, const uint32_t* b) {
    asm volatile(
        "mma.sync.aligned.m16n8k16.row.col.f32.f16.f16.f32 "
        "{%0,%1,%2,%3}, {%4,%5,%6,%7}, {%8,%9}, {%0,%1,%2,%3};"
        : "+f"(d[0]), "+f"(d[1]), "+f"(d[2]), "+f"(d[3])
        : "r"(a[0]), "r"(a[1]), "r"(a[2]), "r"(a[3]), "r"(b[0]), "r"(b[1]));
}
__device__ __forceinline__ void ldm_x4(uint32_t* r, const void* p) {
    uint32_t a = (uint32_t)__cvta_generic_to_shared(p);
    asm volatile("ldmatrix.sync.aligned.m8n8.x4.shared.b16 {%0,%1,%2,%3}, [%4];"
                 : "=r"(r[0]), "=r"(r[1]), "=r"(r[2]), "=r"(r[3]) : "r"(a));
}
__device__ __forceinline__ void ldm_x4_t(uint32_t* r, const void* p) {
    uint32_t a = (uint32_t)__cvta_generic_to_shared(p);
    asm volatile("ldmatrix.sync.aligned.m8n8.x4.trans.shared.b16 {%0,%1,%2,%3}, [%4];"
                 : "=r"(r[0]), "=r"(r[1]), "=r"(r[2]), "=r"(r[3]) : "r"(a));
}
__device__ __forceinline__ void cp_async16(void* dst, const void* src) {
    uint32_t d = (uint32_t)__cvta_generic_to_shared(dst);
    asm volatile("cp.async.cg.shared.global [%0], [%1], 16;" :: "r"(d), "l"(src));
}
#define CP_COMMIT() asm volatile("cp.async.commit_group;" ::: "memory")
#define CP_WAIT2()  asm volatile("cp.async.wait_group 2;" ::: "memory")

// =====================================================================
// Kernel 1: Wh = h @ W^T, tf32 mma, 128n x 256o blocks, 512 threads.
// =====================================================================
__global__ void __launch_bounds__(512, 1) wh_mma_kernel(
    const float* __restrict__ h, const float* __restrict__ W,
    float* __restrict__ Wh, __half* __restrict__ Whh)
{
    extern __shared__ uint32_t sm1[];
    uint32_t* sA = sm1;                      // [2][128][K1ST]
    uint32_t* sB = sm1 + 2 * 128 * K1ST;     // [2][256][K1ST]

    const int t = threadIdx.x, wid = t >> 5, lid = t & 31;
    const int n0 = blockIdx.x * 128;
    const int rh = t >> 2, sh = (t & 3) * 8;
    const int rw = t >> 1, sw = (t & 1) * 16;
    const int wi = wid & 3, wo = wid >> 2;
    const int g = lid >> 2, tig = lid & 3;

    const float* hp = h + (size_t)(n0 + rh) * FDIM + sh;
    const float* wp = W + (size_t)rw * FDIM + sw;

    float d[2][8][4];
#pragma unroll
    for (int mi = 0; mi < 2; mi++)
#pragma unroll
        for (int ni = 0; ni < 8; ni++)
#pragma unroll
            for (int q = 0; q < 4; q++) d[mi][ni][q] = 0.f;

    float4 hr[2], wr[4];

    auto ldg = [&](int it) {
        const int f0 = it * 32;
        hr[0] = *(const float4*)(hp + f0);
        hr[1] = *(const float4*)(hp + f0 + 4);
#pragma unroll
        for (int q = 0; q < 4; q++)
            wr[q] = *(const float4*)(wp + f0 + q * 4);
    };
    auto sts = [&](int bf) {
        uint32_t* ab = sA + bf * 128 * K1ST + rh * K1ST + sh;
        uint32_t* bb = sB + bf * 256 * K1ST + rw * K1ST + sw;
#pragma unroll
        for (int q = 0; q < 2; q++)
            *(uint4*)(ab + q * 4) = make_uint4(to_tf32(hr[q].x), to_tf32(hr[q].y),
                                               to_tf32(hr[q].z), to_tf32(hr[q].w));
#pragma unroll
        for (int q = 0; q < 4; q++)
            *(uint4*)(bb + q * 4) = make_uint4(to_tf32(wr[q].x), to_tf32(wr[q].y),
                                               to_tf32(wr[q].z), to_tf32(wr[q].w));
    };
    auto mma_phase = [&](int bf) {
        const uint32_t* A = sA + bf * 128 * K1ST;
        const uint32_t* B = sB + bf * 256 * K1ST;
#pragma unroll
        for (int ks = 0; ks < 4; ks++) {
            uint32_t af[2][4];
#pragma unroll
            for (int mi = 0; mi < 2; mi++) {
                const int row = wi * 32 + mi * 16 + g;
                const int kc  = ks * 8 + tig;
                af[mi][0] = A[row * K1ST + kc];
                af[mi][1] = A[(row + 8) * K1ST + kc];
                af[mi][2] = A[row * K1ST + kc + 4];
                af[mi][3] = A[(row + 8) * K1ST + kc + 4];
            }
            uint32_t bfr[8][2];
#pragma unroll
            for (int ni = 0; ni < 8; ni++) {
                const int col = wo * 64 + ni * 8 + g;
                const int kc  = ks * 8 + tig;
                bfr[ni][0] = B[col * K1ST + kc];
                bfr[ni][1] = B[col * K1ST + kc + 4];
            }
#pragma unroll
            for (int mi = 0; mi < 2; mi++)
#pragma unroll
                for (int ni = 0; ni < 8; ni++)
                    mma_tf32(d[mi][ni], af[mi], bfr[ni]);
        }
    };

    ldg(0); sts(0); __syncthreads();
    for (int it = 0; it < 8; it++) {
        if (it + 1 < 8) ldg(it + 1);
        mma_phase(it & 1);
        if (it + 1 < 8) sts((it + 1) & 1);
        __syncthreads();
    }

#pragma unroll
    for (int mi = 0; mi < 2; mi++) {
        const int r0 = wi * 32 + mi * 16 + g;
        const int r1 = r0 + 8;
        float*  o0p = Wh + (size_t)(n0 + r0) * FDIM + wo * 64 + tig * 2;
        float*  o1p = Wh + (size_t)(n0 + r1) * FDIM + wo * 64 + tig * 2;
        __half* h0p = Whh + (size_t)(n0 + r0) * FDIM + wo * 64 + tig * 2;
        __half* h1p = Whh + (size_t)(n0 + r1) * FDIM + wo * 64 + tig * 2;
#pragma unroll
        for (int ni = 0; ni < 8; ni++) {
            *(float2*)(o0p + ni * 8) = make_float2(d[mi][ni][0], d[mi][ni][1]);
            *(float2*)(o1p + ni * 8) = make_float2(d[mi][ni][2], d[mi][ni][3]);
            *(__half2*)(h0p + ni * 8) =
                __float22half2_rn(make_float2(d[mi][ni][0], d[mi][ni][1]));
            *(__half2*)(h1p + ni * 8) =
                __float22half2_rn(make_float2(d[mi][ni][2], d[mi][ni][3]));
        }
    }
}

// =====================================================================
// Kernel 2: per-row f1,f2 -> E1, F1, (E2,F2)
// =====================================================================
__global__ void __launch_bounds__(256) fvec_kernel(
    const float* __restrict__ Wh, const float* __restrict__ a,
    float* __restrict__ E1, float* __restrict__ F1, float2* __restrict__ EF)
{
    const int row  = blockIdx.x * 8 + (threadIdx.x >> 5);
    const int lane = threadIdx.x & 31;
    const float4* wr = (const float4*)(Wh + (size_t)row * FDIM);
    const float4* a1 = (const float4*)a;
    const float4* a2 = (const float4*)(a + FDIM);

    float4 x0 = wr[lane], x1 = wr[lane + 32];
    float4 p0 = a1[lane], p1 = a1[lane + 32];
    float4 q0 = a2[lane], q1 = a2[lane + 32];

    float s1 = x0.x * p0.x + x0.y * p0.y + x0.z * p0.z + x0.w * p0.w
             + x1.x * p1.x + x1.y * p1.y + x1.z * p1.z + x1.w * p1.w;
    float s2 = x0.x * q0.x + x0.y * q0.y + x0.z * q0.z + x0.w * q0.w
             + x1.x * q1.x + x1.y * q1.y + x1.z * q1.z + x1.w * q1.w;
#pragma unroll
    for (int o = 16; o; o >>= 1) {
        s1 += __shfl_xor_sync(0xFFFFFFFFu, s1, o);
        s2 += __shfl_xor_sync(0xFFFFFFFFu, s2, o);
    }
    if (lane == 0) {
        E1[row] = __expf(s1);
        F1[row] = __expf(0.2f * s1);
        EF[row] = make_float2(__expf(s2), __expf(0.2f * s2));
    }
}

// =====================================================================
// Kernel 2.5 (wgen): fp16 w matrix + fp32 row denominators (streaming).
// =====================================================================
__global__ void __launch_bounds__(512) wgen_kernel(
    const int* __restrict__ adj,
    const float* __restrict__ E1, const float* __restrict__ F1,
    const float2* __restrict__ EF,
    __half* __restrict__ wmat, float* __restrict__ den)
{
    __shared__ float2 sEF[NROW];   // 16 KB
    const int t = threadIdx.x, wrp = t >> 5, lane = t & 31;
    const int bz = blockIdx.y;

    {
        const float4* src = (const float4*)(EF + bz * NROW);
        float4* dst = (float4*)sEF;
        dst[t]       = src[t];
        dst[t + 512] = src[t + 512];
    }
    __syncthreads();

    const int row_g = bz * NROW + blockIdx.x * 16 + wrp;
    const float E1r  = E1[row_g], F1r = F1[row_g];
    const float tinv = __frcp_rn(E1r);            // s>0  <=>  E2_j > 1/E1_i

    const int4* ap = (const int4*)(adj + (size_t)row_g * NROW);
    __half* wp = wmat + (size_t)row_g * NROW;

    float dn = 0.f;
#pragma unroll 4
    for (int c = 0; c < 16; c++) {
        const int j0 = c * 128 + lane * 4;
        const int4 am = __ldg(ap + c * 32 + lane);
        const float4 efa = *(const float4*)(sEF + j0);
        const float4 efb = *(const float4*)(sEF + j0 + 2);
        float w0 = am.x ? (efa.x > tinv ? E1r * efa.x : F1r * efa.y) : 0.f;
        float w1 = am.y ? (efa.z > tinv ? E1r * efa.z : F1r * efa.w) : 0.f;
        float w2 = am.z ? (efb.x > tinv ? E1r * efb.x : F1r * efb.y) : 0.f;
        float w3 = am.w ? (efb.z > tinv ? E1r * efb.z : F1r * efb.w) : 0.f;
        dn += (w0 + w1) + (w2 + w3);
        __half2 p0 = __float22half2_rn(make_float2(w0, w1));
        __half2 p1 = __float22half2_rn(make_float2(w2, w3));
        uint2 pk = make_uint2(*(uint32_t*)&p0, *(uint32_t*)&p1);
        *(uint2*)(wp + j0) = pk;
    }
#pragma unroll
    for (int o = 16; o; o >>= 1)
        dn += __shfl_xor_sync(0xFFFFFFFFu, dn, o);
    if (lane == 0) den[row_g] = dn;
}

// =====================================================================
// Kernel 3: pure fp16 GEMM, 128i x 128o, 256 threads, 2 blocks/SM,
// depth-4 ring, per-chunk wait (overlap of fetch with mma preserved).
// =====================================================================
#define AST3 40            // A tile row stride (halves): 32 + 8 pad
#define BST3 136           // B tile k-row stride (halves): 128 + 8 pad
#define A_SLOT (128 * AST3 * 2)   // 10240 B
#define B_SLOT (32 * BST3 * 2)    //  8704 B
// smem layout (bytes)
#define OFF_A   0          // A ring: 4 * 10240 = 40960
#define OFF_B   40960      // B ring: 4 * 8704  = 34816
#define SM3_SZ  75776

__global__ void __launch_bounds__(256, 2) attn_f16_kernel(
    const __half* __restrict__ wmat,
    const __half* __restrict__ Whh,
    const float* __restrict__ den,
    float* __restrict__ out)
{
    extern __shared__ char smc[];
    __half* smA = (__half*)(smc + OFF_A);
    __half* smB = (__half*)(smc + OFF_B);

    const int t = threadIdx.x, wid = t >> 5, lid = t & 31;
    const int bz = blockIdx.z, i0 = blockIdx.x * 128, o0 = blockIdx.y * 128;
    const int wi = wid & 3, wo = wid >> 2;       // warp tile: rows wi*32, cols wo*64
    const int g  = lid >> 2, tig = lid & 3;

    // cp.async sources
    // A: w row (t>>1), 32B seg (t&1) of the 64B chunk-row
    const char* w_src   = (const char*)(wmat + (size_t)(bz * NROW + i0 + (t >> 1)) * NROW)
                          + (t & 1) * 32;
    // B: Whh k-row (t>>3), 32B seg (t&7) of the 256B row slice at o0
    const char* whh_src = (const char*)(Whh + (size_t)(bz * NROW + (t >> 3)) * FDIM + o0)
                          + (t & 7) * 32;

    auto stage = [&](int c) {
        const int slot = c & 3;
        {
            char* dst = (char*)smA + slot * A_SLOT
                        + (t >> 1) * (AST3 * 2) + (t & 1) * 32;
            const char* src = w_src + (size_t)c * (KJ * 2);
            cp_async16(dst, src);
            cp_async16(dst + 16, src + 16);
        }
        {
            char* dst = (char*)smB + slot * B_SLOT
                        + (t >> 3) * (BST3 * 2) + (t & 7) * 32;
            const char* src = whh_src + (size_t)c * (KJ * FDIM * 2);
            cp_async16(dst, src);
            cp_async16(dst + 16, src + 16);
        }
    };

    float d[2][8][4];
#pragma unroll
    for (int mi = 0; mi < 2; mi++)
#pragma unroll
        for (int ni = 0; ni < 8; ni++)
#pragma unroll
            for (int q = 0; q < 4; q++) d[mi][ni][q] = 0.f;

    auto mma_phase = [&](int c) {
        const __half* A = smA + (c & 3) * (128 * AST3);
        const __half* B = smB + (c & 3) * (32 * BST3);
#pragma unroll
        for (int ks = 0; ks < 2; ks++) {
            uint32_t af[2][4];
#pragma unroll
            for (int mi = 0; mi < 2; mi++)
                ldm_x4(af[mi], A + (wi * 32 + mi * 16 + (lid & 15)) * AST3
                               + ks * 16 + (lid >> 4) * 8);
            uint32_t bf4[4][4];
#pragma unroll
            for (int np = 0; np < 4; np++)
                ldm_x4_t(bf4[np], B + (ks * 16 + (lid & 7) + ((lid >> 3) & 1) * 8) * BST3
                                  + wo * 64 + np * 16 + (lid >> 4) * 8);
#pragma unroll
            for (int mi = 0; mi < 2; mi++)
#pragma unroll
                for (int ni = 0; ni < 8; ni++)
                    mma_f16(d[mi][ni], af[mi], &bf4[ni >> 1][(ni & 1) * 2]);
        }
    };

    // ---- pipeline: 3 stages in flight, per-chunk wait (distance 3) ----
    stage(0); CP_COMMIT();
    stage(1); CP_COMMIT();
    stage(2); CP_COMMIT();

    for (int c = 0; c < NIT; c++) {
        CP_WAIT2();                  // groups <= c complete (commits = c+3)
        __syncthreads();             // slot c visible to all; mma(c-1) retired
        if (c + 3 < NIT) stage(c + 3);
        CP_COMMIT();                 // uniform group numbering
        mma_phase(c);
    }

    // ---- epilogue ----
    const float* denb = den + bz * NROW + i0;
#pragma unroll
    for (int mi = 0; mi < 2; mi++) {
        const int r0 = wi * 32 + mi * 16 + g;
        const int r1 = r0 + 8;
        const float inv0 = 1.0f / denb[r0];
        const float inv1 = 1.0f / denb[r1];
        float* op0 = out + (size_t)(bz * NROW + i0 + r0) * FDIM + o0 + wo * 64 + tig * 2;
        float* op1 = out + (size_t)(bz * NROW + i0 + r1) * FDIM + o0 + wo * 64 + tig * 2;
#pragma unroll
        for (int ni = 0; ni < 8; ni++) {
            *(float2*)(op0 + ni * 8) = make_float2(d[mi][ni][0] * inv0, d[mi][ni][1] * inv0);
            *(float2*)(op1 + ni * 8) = make_float2(d[mi][ni][2] * inv1, d[mi][ni][3] * inv1);
        }
    }
}

// =====================================================================
extern "C" void kernel_launch(void* const* d_in, const int* in_sizes, int n_in,
                              void* d_out, int out_size)
{
    const float* h   = (const float*)d_in[0];
    const int*   adj = (const int*)  d_in[1];
    const float* W   = (const float*)d_in[2];
    const float* a   = (const float*)d_in[3];
    float* out = (float*)d_out;

    float *Wh, *E1, *F1, *den;
    float2* EFp;
    __half *Whh, *wmat;
    cudaGetSymbolAddress((void**)&Wh,   g_Wh);
    cudaGetSymbolAddress((void**)&Whh,  g_Whh);
    cudaGetSymbolAddress((void**)&E1,   g_E1);
    cudaGetSymbolAddress((void**)&F1,   g_F1);
    cudaGetSymbolAddress((void**)&EFp,  g_EF);
    cudaGetSymbolAddress((void**)&wmat, g_W);
    cudaGetSymbolAddress((void**)&den,  g_den);

    const int smem1 = (2 * 128 * K1ST + 2 * 256 * K1ST) * (int)sizeof(uint32_t); // 110592
    cudaFuncSetAttribute(wh_mma_kernel,   cudaFuncAttributeMaxDynamicSharedMemorySize, smem1);
    cudaFuncSetAttribute(attn_f16_kernel, cudaFuncAttributeMaxDynamicSharedMemorySize, SM3_SZ);

    wh_mma_kernel<<<NTOT / 128, 512, smem1>>>(h, W, Wh, Whh);
    fvec_kernel<<<NTOT / 8, 256>>>(Wh, a, E1, F1, EFp);
    wgen_kernel<<<dim3(NROW / 16, NBATCH), 512>>>(adj, E1, F1, EFp, wmat, den);
    attn_f16_kernel<<<dim3(NROW / 128, FDIM / 128, NBATCH), 256, SM3_SZ>>>(
        wmat, Whh, den, out);
}